// round 1
// baseline (speedup 1.0000x reference)
#include <cuda_runtime.h>
#include <math.h>
#include <stdint.h>

#define NN 128
#define DD 2048
#define EPSF 1e-12f
#define MARGINF 0.3f
#define NKC 16          // split-K chunks
#define KCHUNK 128      // K per chunk (16*128 = 2048)

// ---------------- device scratch (no allocations allowed) ----------------
__device__ float g_part[NKC][NN * NN];   // split-K partial dot products (1 MB)
__device__ float g_norm[2 * NN];         // row norms: [0,128)=f1, [128,256)=f2
__device__ float g_dist_ap[NN];
__device__ int   g_sel1[NN];
__device__ int   g_sel2[NN];
__device__ float g_trip[NN];
__device__ int   g_done;

// ---------------- Kernel 1: split-K GEMM (f1 @ f2^T partials) + norms ----
// grid (4,4,17), block 64.
//   z < 16 : compute 32x32 tile (x=i-tile, y=j-tile) over K-chunk z
//   z == 16: 16 blocks compute row norms of [f1;f2] (16 rows each) + reset g_done
__global__ void k_gemm(const float* __restrict__ f1, const float* __restrict__ f2) {
    const int kc = blockIdx.z;
    const int tid = threadIdx.x;

    if (kc == NKC) {
        // ---- norms branch ----
        const int id = blockIdx.y * 4 + blockIdx.x;   // 0..15
        const int w = tid >> 5, lane = tid & 31;      // 2 warps
        for (int rr = w * 8; rr < w * 8 + 8; rr++) {
            const int row = id * 16 + rr;             // 0..255
            const float4* p4 = (const float4*)((row < NN) ? (f1 + row * DD)
                                                          : (f2 + (row - NN) * DD));
            float s = 0.f;
            #pragma unroll 4
            for (int t = lane; t < DD / 4; t += 32) {
                float4 v = p4[t];
                s += v.x * v.x + v.y * v.y + v.z * v.z + v.w * v.w;
            }
            #pragma unroll
            for (int o = 16; o; o >>= 1) s += __shfl_xor_sync(0xffffffffu, s, o);
            if (lane == 0) g_norm[row] = s;
        }
        if (id == 0 && tid == 0) g_done = 0;
        return;
    }

    // ---- GEMM branch ----
    __shared__ float As[32][129];   // padded: bank = (r + k) % 32 -> conflict-free reads
    __shared__ float Bs[32][129];

    const int i0 = blockIdx.x * 32;
    const int j0 = blockIdx.y * 32;
    const int k0 = kc * KCHUNK;

    // load tiles (coalesced float4 global reads)
    #pragma unroll
    for (int t = tid; t < 1024; t += 64) {
        const int rr = t >> 5;        // 0..31
        const int c4 = t & 31;        // float4 index within 128-wide K chunk
        float4 va = *(const float4*)(f1 + (i0 + rr) * DD + k0 + c4 * 4);
        As[rr][c4 * 4 + 0] = va.x; As[rr][c4 * 4 + 1] = va.y;
        As[rr][c4 * 4 + 2] = va.z; As[rr][c4 * 4 + 3] = va.w;
        float4 vb = *(const float4*)(f2 + (j0 + rr) * DD + k0 + c4 * 4);
        Bs[rr][c4 * 4 + 0] = vb.x; Bs[rr][c4 * 4 + 1] = vb.y;
        Bs[rr][c4 * 4 + 2] = vb.z; Bs[rr][c4 * 4 + 3] = vb.w;
    }
    __syncthreads();

    const int r0 = (tid >> 3) * 4;    // 8 row-groups
    const int c0 = (tid & 7) * 4;     // 8 col-groups

    float acc[4][4] = {};
    #pragma unroll 8
    for (int k = 0; k < KCHUNK; k++) {
        float a0 = As[r0 + 0][k], a1 = As[r0 + 1][k], a2 = As[r0 + 2][k], a3 = As[r0 + 3][k];
        float b0 = Bs[c0 + 0][k], b1 = Bs[c0 + 1][k], b2 = Bs[c0 + 2][k], b3 = Bs[c0 + 3][k];
        acc[0][0] += a0 * b0; acc[0][1] += a0 * b1; acc[0][2] += a0 * b2; acc[0][3] += a0 * b3;
        acc[1][0] += a1 * b0; acc[1][1] += a1 * b1; acc[1][2] += a1 * b2; acc[1][3] += a1 * b3;
        acc[2][0] += a2 * b0; acc[2][1] += a2 * b1; acc[2][2] += a2 * b2; acc[2][3] += a2 * b3;
        acc[3][0] += a3 * b0; acc[3][1] += a3 * b1; acc[3][2] += a3 * b2; acc[3][3] += a3 * b3;
    }

    float* dst = &g_part[kc][0];
    #pragma unroll
    for (int m = 0; m < 4; m++) {
        float4 v = make_float4(acc[m][0], acc[m][1], acc[m][2], acc[m][3]);
        *(float4*)&dst[(i0 + r0 + m) * NN + j0 + c0] = v;
    }
}

// ---------------- Kernel 2: distances + hard example selection -----------
// grid 128 (row i), block 128 (col j)
__global__ void k_distsel(const int* __restrict__ tgt) {
    const int i = blockIdx.x;
    const int j = threadIdx.x;

    __shared__ int   st[NN];
    __shared__ float s_ap[4];
    __shared__ unsigned long long s_k1[4], s_k2[4];

    st[j] = tgt[j];

    // reduce split-K partials
    float dot = 0.f;
    #pragma unroll
    for (int kc = 0; kc < NKC; kc++) dot += g_part[kc][i * NN + j];

    float d2 = g_norm[i] + g_norm[NN + j] - 2.f * dot;
    float d = sqrtf(fmaxf(d2, EPSF));

    __syncthreads();
    const int ti = st[i];
    const bool pos = (st[j] == ti);

    // rank of j among negatives (ascending column order)
    int rank = 0;
    #pragma unroll 8
    for (int q = 0; q < NN; q++)
        rank += (q < j && st[q] != ti) ? 1 : 0;

    float apv = pos ? d : -INFINITY;
    // key encodes (distance, column) lexicographically: min-key => argmin with
    // first-occurrence tie-break (d > 0 so float bits are order-preserving)
    unsigned long long key =
        ((unsigned long long)__float_as_uint(d) << 32) | (unsigned)j;
    unsigned long long k1 = (!pos && rank < 56) ? key : ~0ull;
    unsigned long long k2 = (!pos && rank >= 56 && rank < 112) ? key : ~0ull;

    #pragma unroll
    for (int o = 16; o; o >>= 1) {
        apv = fmaxf(apv, __shfl_xor_sync(0xffffffffu, apv, o));
        unsigned long long t1 = __shfl_xor_sync(0xffffffffu, k1, o);
        unsigned long long t2 = __shfl_xor_sync(0xffffffffu, k2, o);
        k1 = (t1 < k1) ? t1 : k1;
        k2 = (t2 < k2) ? t2 : k2;
    }
    const int w = j >> 5;
    if ((j & 31) == 0) { s_ap[w] = apv; s_k1[w] = k1; s_k2[w] = k2; }
    __syncthreads();
    if (j == 0) {
        float ap = s_ap[0];
        unsigned long long m1 = s_k1[0], m2 = s_k2[0];
        #pragma unroll
        for (int q = 1; q < 4; q++) {
            ap = fmaxf(ap, s_ap[q]);
            if (s_k1[q] < m1) m1 = s_k1[q];
            if (s_k2[q] < m2) m2 = s_k2[q];
        }
        g_dist_ap[i] = ap;
        g_sel1[i] = (int)(m1 & 0xffffffffull);
        g_sel2[i] = (int)(m2 & 0xffffffffull);
    }
}

// ---------------- Kernel 3: dist_an + triplets + finalize ----------------
// grid 128 (anchor k), block 256
__global__ void k_distan(const float* __restrict__ f1, float* __restrict__ out,
                         int out_size) {
    const int k = blockIdx.x;
    const int tid = threadIdx.x;

    // index shuffle: feat_rgb_mid / feat_ir_mid mapping, anchor is always f1[k]
    int m = (k < 32) ? k : (k < 64) ? (k + 32) : (k < 96) ? (k - 32) : k;
    const int a = g_sel1[m];
    const int b = g_sel2[m];

    const float4* xk = (const float4*)(f1 + k * DD);
    const float4* xa = (const float4*)(f1 + a * DD);
    const float4* xb = (const float4*)(f1 + b * DD);

    float aa = 0.f, bb = 0.f, ab = 0.f;
    #pragma unroll
    for (int t = tid; t < DD / 4; t += 256) {
        float4 vk = xk[t], va = xa[t], vb = xb[t];
        float4 fm;
        fm.x = 0.5f * (va.x + vb.x); fm.y = 0.5f * (va.y + vb.y);
        fm.z = 0.5f * (va.z + vb.z); fm.w = 0.5f * (va.w + vb.w);
        aa += vk.x * vk.x + vk.y * vk.y + vk.z * vk.z + vk.w * vk.w;
        bb += fm.x * fm.x + fm.y * fm.y + fm.z * fm.z + fm.w * fm.w;
        ab += vk.x * fm.x + vk.y * fm.y + vk.z * fm.z + vk.w * fm.w;
    }
    #pragma unroll
    for (int o = 16; o; o >>= 1) {
        aa += __shfl_xor_sync(0xffffffffu, aa, o);
        bb += __shfl_xor_sync(0xffffffffu, bb, o);
        ab += __shfl_xor_sync(0xffffffffu, ab, o);
    }
    __shared__ float red[8][3];
    const int w = tid >> 5;
    if ((tid & 31) == 0) { red[w][0] = aa; red[w][1] = bb; red[w][2] = ab; }
    __syncthreads();

    if (tid == 0) {
        float saa = 0.f, sbb = 0.f, sab = 0.f;
        #pragma unroll
        for (int q = 0; q < 8; q++) { saa += red[q][0]; sbb += red[q][1]; sab += red[q][2]; }
        float d2 = saa + sbb - 2.f * sab;
        float dan = sqrtf(fmaxf(d2, EPSF));
        g_trip[k] = g_dist_ap[k] - dan + MARGINF;

        __threadfence();
        int done = atomicAdd(&g_done, 1);
        if (done == NN - 1) {
            // deterministic serial finalize
            float s = 0.f; int c = 0;
            #pragma unroll 8
            for (int q = 0; q < NN; q++) {
                float t = g_trip[q];
                if (t > 0.f) { s += t; c++; }
            }
            out[0] = s * (1.0f / 128.0f);
            if (out_size > 1) out[1] = (float)c;
        }
    }
}

// ---------------- launch ----------------
extern "C" void kernel_launch(void* const* d_in, const int* in_sizes, int n_in,
                              void* d_out, int out_size) {
    const float* f1 = (const float*)d_in[0];
    const float* f2 = (const float*)d_in[1];
    const int*   tgt = (const int*)d_in[2];
    (void)in_sizes; (void)n_in;

    k_gemm<<<dim3(4, 4, NKC + 1), 64>>>(f1, f2);
    k_distsel<<<NN, NN>>>(tgt);
    k_distan<<<NN, 256>>>(f1, (float*)d_out, out_size);
}